// round 12
// baseline (speedup 1.0000x reference)
#include <cuda_runtime.h>
#include <cuda_bf16.h>
#include <math.h>
#include <stdint.h>

// SlotAttention GB300 — Round 11: phase-1 logits on HMMA (mma.sync bf16 x3
// compensation, fragment scheme verbatim from the verified R2 kernel),
// softmax on fragments, phase 2 (updates) stays fp32 SIMT (R10-proven).

#define Bb 64
#define Nn 4096
#define Dd 256
#define Kk 15
#define Hh 512
#define BN_TOT (Bb * Nn)   // 262144
#define BK_TOT (Bb * Kk)   // 960
#define NCH 32             // n-chunks per batch
#define CHN 128            // n per chunk
#define SROW 72            // x̂ smem row stride (bf16), R2-style conflict-free
#define QROW 264           // q smem row stride (bf16)
#define AS2 132            // attn smem row stride (floats)

// dynamic smem byte offsets for attn_pass
#define SM_XH 0
#define SM_XL 18432
#define SM_QH 36864
#define SM_QL 45312
#define SM_AS 53760
#define SM_BYTES 61680

// ---------------- scratch ----------------
__device__ float g_xln[(size_t)BN_TOT * Dd];            // 256 MiB fp32
__device__ __nv_bfloat16 g_xhi[(size_t)BN_TOT * Dd];    // 128 MiB
__device__ __nv_bfloat16 g_xlo[(size_t)BN_TOT * Dd];    // 128 MiB
__device__ float g_wqk[Dd * Dd];
__device__ float g_wiv[3 * Dd * Dd];
__device__ float g_slots[BK_TOT * Dd];
__device__ __nv_bfloat16 g_qhi[BK_TOT * Dd];
__device__ __nv_bfloat16 g_qlo[BK_TOT * Dd];
__device__ float g_part[BK_TOT * NCH];
__device__ float g_updpart[(size_t)NCH * BK_TOT * Dd];  // 31.5 MB

// ---------------- helpers ----------------
__device__ __forceinline__ float warp_sum(float v) {
#pragma unroll
    for (int o = 16; o > 0; o >>= 1) v += __shfl_xor_sync(0xffffffffu, v, o);
    return v;
}
__device__ __forceinline__ float sigmoidf_(float x) { return 1.0f / (1.0f + __expf(-x)); }

__device__ __forceinline__ uint32_t smem_u32(const void* p) {
    uint32_t a;
    asm("{ .reg .u64 t; cvta.to.shared.u64 t, %1; cvt.u32.u64 %0, t; }" : "=r"(a) : "l"(p));
    return a;
}
__device__ __forceinline__ void ldsm_x4(uint32_t& r0, uint32_t& r1, uint32_t& r2, uint32_t& r3,
                                        uint32_t addr) {
    asm volatile("ldmatrix.sync.aligned.m8n8.x4.shared.b16 {%0,%1,%2,%3}, [%4];"
                 : "=r"(r0), "=r"(r1), "=r"(r2), "=r"(r3) : "r"(addr));
}
__device__ __forceinline__ void mma_bf16(float* c, uint32_t a0, uint32_t a1, uint32_t a2,
                                         uint32_t a3, uint32_t b0, uint32_t b1) {
    asm volatile(
        "mma.sync.aligned.m16n8k16.row.col.f32.bf16.bf16.f32 "
        "{%0,%1,%2,%3}, {%4,%5,%6,%7}, {%8,%9}, {%0,%1,%2,%3};"
        : "+f"(c[0]), "+f"(c[1]), "+f"(c[2]), "+f"(c[3])
        : "r"(a0), "r"(a1), "r"(a2), "r"(a3), "r"(b0), "r"(b1));
}

template <int K4>
__device__ __forceinline__ void dot4(float acc[8], const float* S, int srow,
                                     const float* __restrict__ Wrow) {
    const float4* w4 = (const float4*)Wrow;
#pragma unroll 4
    for (int d4 = 0; d4 < K4; d4++) {
        float4 w = w4[d4];
#pragma unroll
        for (int r = 0; r < 8; r++) {
            const float4 sv = *(const float4*)(S + r * srow + d4 * 4);
            acc[r] += sv.x * w.x + sv.y * w.y + sv.z * w.z + sv.w * w.w;
        }
    }
}

__device__ __forceinline__ void warp_ln_row(const float* src, float* dst,
                                            const float* __restrict__ w,
                                            const float* __restrict__ b, int lane) {
    float vals[8];
    float s = 0.f, s2 = 0.f;
#pragma unroll
    for (int k = 0; k < 8; k++) {
        float v = src[lane + 32 * k];
        vals[k] = v; s += v; s2 += v * v;
    }
    s = warp_sum(s); s2 = warp_sum(s2);
    float m = s * (1.0f / 256.0f);
    float rs = rsqrtf(s2 * (1.0f / 256.0f) - m * m + 1e-5f);
#pragma unroll
    for (int k = 0; k < 8; k++) {
        int d = lane + 32 * k;
        dst[d] = (vals[k] - m) * rs * w[d] + b[d];
    }
}

// ---------------- big LN over inputs → fp32 + bf16 hi/lo ----------------
__global__ void ln_apply_kernel(const float* __restrict__ x,
                                const float* __restrict__ w, const float* __restrict__ bb) {
    int row = blockIdx.x * 8 + threadIdx.y;
    int lane = threadIdx.x;
    const float* xr = x + (size_t)row * Dd;
    float v[8];
    float s = 0.f, s2 = 0.f;
#pragma unroll
    for (int j = 0; j < 8; j++) {
        v[j] = xr[j * 32 + lane];
        s += v[j]; s2 += v[j] * v[j];
    }
    s = warp_sum(s); s2 = warp_sum(s2);
    float m = s * (1.0f / 256.0f);
    float rs = rsqrtf(s2 * (1.0f / 256.0f) - m * m + 1e-5f);
#pragma unroll
    for (int j = 0; j < 8; j++) {
        int dd = j * 32 + lane;
        float y = (v[j] - m) * rs * w[dd] + bb[dd];
        size_t idx = (size_t)row * Dd + dd;
        g_xln[idx] = y;
        __nv_bfloat16 hi = __float2bfloat16(y);
        g_xhi[idx] = hi;
        g_xlo[idx] = __float2bfloat16(y - __bfloat162float(hi));
    }
}

// ---------------- precompute: C[e][d] = Σ_j X[j][e]·Y[j][d]  (XᵀY) ----------------
__global__ __launch_bounds__(256) void atb_kernel(const float* __restrict__ X,
                                                  const float* __restrict__ Y,
                                                  float* __restrict__ C) {
    __shared__ float Xs[16][68];
    __shared__ float Ys[16][68];
    int e0 = blockIdx.x * 64, d0 = blockIdx.y * 64;
    int tid = threadIdx.x;
    int row_t = tid >> 4, col_t = tid & 15;
    int jr = tid >> 4, c4 = (tid & 15) << 2;
    float acc[4][4];
#pragma unroll
    for (int i = 0; i < 4; i++)
#pragma unroll
        for (int j = 0; j < 4; j++) acc[i][j] = 0.f;
    for (int jb = 0; jb < 256; jb += 16) {
        float4 xv = *(const float4*)(X + (size_t)(jb + jr) * Dd + e0 + c4);
        Xs[jr][c4 + 0] = xv.x; Xs[jr][c4 + 1] = xv.y;
        Xs[jr][c4 + 2] = xv.z; Xs[jr][c4 + 3] = xv.w;
        float4 yv = *(const float4*)(Y + (size_t)(jb + jr) * Dd + d0 + c4);
        Ys[jr][c4 + 0] = yv.x; Ys[jr][c4 + 1] = yv.y;
        Ys[jr][c4 + 2] = yv.z; Ys[jr][c4 + 3] = yv.w;
        __syncthreads();
#pragma unroll
        for (int k = 0; k < 16; k++)
#pragma unroll
            for (int i = 0; i < 4; i++)
#pragma unroll
                for (int j = 0; j < 4; j++)
                    acc[i][j] += Xs[k][row_t * 4 + i] * Ys[k][col_t * 4 + j];
        __syncthreads();
    }
#pragma unroll
    for (int i = 0; i < 4; i++)
#pragma unroll
        for (int j = 0; j < 4; j++)
            C[(size_t)(e0 + row_t * 4 + i) * Dd + d0 + col_t * 4 + j] = acc[i][j];
}

// ---------------- precompute: C[g][e] = Σ_d A[g][d]·B[d][e]  (A·B) ----------------
__global__ __launch_bounds__(256) void ab_kernel(const float* __restrict__ A,
                                                 const float* __restrict__ B,
                                                 float* __restrict__ C) {
    __shared__ float As[16][68];
    __shared__ float Bs[16][68];
    int g0 = blockIdx.x * 64, e0 = blockIdx.y * 64;
    int tid = threadIdx.x;
    int row_t = tid >> 4, col_t = tid & 15;
    int r = tid >> 2, k4 = (tid & 3) << 2;
    int jr = tid >> 4, c4 = (tid & 15) << 2;
    float acc[4][4];
#pragma unroll
    for (int i = 0; i < 4; i++)
#pragma unroll
        for (int j = 0; j < 4; j++) acc[i][j] = 0.f;
    for (int db = 0; db < 256; db += 16) {
        float4 av = *(const float4*)(A + (size_t)(g0 + r) * Dd + db + k4);
        As[k4 + 0][r] = av.x; As[k4 + 1][r] = av.y;
        As[k4 + 2][r] = av.z; As[k4 + 3][r] = av.w;
        float4 bv = *(const float4*)(B + (size_t)(db + jr) * Dd + e0 + c4);
        Bs[jr][c4 + 0] = bv.x; Bs[jr][c4 + 1] = bv.y;
        Bs[jr][c4 + 2] = bv.z; Bs[jr][c4 + 3] = bv.w;
        __syncthreads();
#pragma unroll
        for (int k = 0; k < 16; k++)
#pragma unroll
            for (int i = 0; i < 4; i++)
#pragma unroll
                for (int j = 0; j < 4; j++)
                    acc[i][j] += As[k][row_t * 4 + i] * Bs[k][col_t * 4 + j];
        __syncthreads();
    }
#pragma unroll
    for (int i = 0; i < 4; i++)
#pragma unroll
        for (int j = 0; j < 4; j++)
            C[(size_t)(g0 + row_t * 4 + i) * Dd + e0 + col_t * 4 + j] = acc[i][j];
}

// ---------------- slots init ----------------
__global__ void slots_init_kernel(const float* __restrict__ mu,
                                  const float* __restrict__ ls,
                                  const float* __restrict__ noise) {
    int i = blockIdx.x * 256 + threadIdx.x;
    int kd = i % (Kk * Dd);
    g_slots[i] = mu[kd] + __expf(ls[kd]) * noise[i];
}

__device__ __forceinline__ void store_q_hilo(int row, int t, float qv) {
    __nv_bfloat16 hi = __float2bfloat16(qv);
    g_qhi[(size_t)row * Dd + t] = hi;
    g_qlo[(size_t)row * Dd + t] = __float2bfloat16(qv - __bfloat162float(hi));
}

// ---------------- ln_slots + q (before first iteration) ----------------
__global__ __launch_bounds__(256) void slot_lnq_kernel(const float* __restrict__ lns_w,
                                                       const float* __restrict__ lns_b) {
    __shared__ float a_s[8][256];
    int t = threadIdx.x, lane = t & 31, wid = t >> 5;
    int row0 = blockIdx.x * 8;
    warp_ln_row(g_slots + (size_t)(row0 + wid) * Dd, &a_s[wid][0], lns_w, lns_b, lane);
    __syncthreads();
    float qa[8] = {0, 0, 0, 0, 0, 0, 0, 0};
    dot4<64>(qa, &a_s[0][0], 256, g_wqk + (size_t)t * Dd);
#pragma unroll
    for (int r = 0; r < 8; r++) store_q_hilo(row0 + r, t, qa[r]);
}

// ---------------- fused attention pass: HMMA logits + fragment softmax + fp32 updates
// grid (NCH, Bb), block 256 (8 warps; warp w owns n-rows w*16..w*16+15).
__global__ __launch_bounds__(256) void attn_pass_kernel(float* __restrict__ attn_out,
                                                        int final_pass) {
    extern __shared__ char smc[];
    uint32_t sb = smem_u32(smc);
    float* as_ = (float*)(smc + SM_AS);
    int b = blockIdx.y, chunk = blockIdx.x, t = threadIdx.x;
    int wid = t >> 5, lane = t & 31;

    // stage q hi/lo: 16 rows x 256 (row 15 = zeros), stride QROW
    {
        const float4* qh4 = (const float4*)(g_qhi + (size_t)b * Kk * Dd);
        const float4* ql4 = (const float4*)(g_qlo + (size_t)b * Kk * Dd);
        float4 z = make_float4(0.f, 0.f, 0.f, 0.f);
#pragma unroll
        for (int i = t; i < 16 * 32; i += 256) {
            int row = i >> 5, col8 = i & 31;          // col8: 8 bf16 per float4
            int so = (row * QROW + col8 * 8) * 2;
            bool ok = row < Kk;
            *(float4*)(smc + SM_QH + so) = ok ? qh4[row * 32 + col8] : z;
            *(float4*)(smc + SM_QL + so) = ok ? ql4[row * 32 + col8] : z;
        }
    }

    int n_glob0 = chunk * CHN;                         // 128-n chunk
    // fragment addressing (R2 scheme)
    int a_row = wid * 16 + (lane & 15);
    int a_koff = (lane >> 4) << 3;
    int b_row = (lane & 7) + ((lane >> 4) << 3);
    int b_koff = ((lane >> 3) & 1) << 3;

    float acc0[8], acc1[8];                            // tiles: slots 0-7, 8-15
#pragma unroll
    for (int i = 0; i < 8; i++) { acc0[i] = 0.f; acc1[i] = 0.f; }
    float* c0 = acc0;                                  // [tile0 rows r,r+8]
    float* c1 = acc1;

    for (int c = 0; c < 4; c++) {                      // k-chunks of 64 d
        __syncthreads();
        // stage x̂ hi/lo: 128 rows x 64 d, stride SROW
        const float4* xh4 = (const float4*)(g_xhi + ((size_t)b * Nn + n_glob0) * Dd + c * 64);
        const float4* xl4 = (const float4*)(g_xlo + ((size_t)b * Nn + n_glob0) * Dd + c * 64);
#pragma unroll
        for (int i = t; i < 128 * 8; i += 256) {
            int row = i >> 3, col8 = i & 7;
            int so = (row * SROW + col8 * 8) * 2;
            *(float4*)(smc + SM_XH + so) = xh4[(size_t)row * 32 + col8];
            *(float4*)(smc + SM_XL + so) = xl4[(size_t)row * 32 + col8];
        }
        __syncthreads();
#pragma unroll
        for (int ks = 0; ks < 4; ks++) {
            int kk = ks * 16;
            uint32_t ah0, ah1, ah2, ah3, al0, al1, al2, al3;
            uint32_t aoff = (uint32_t)(a_row * SROW + kk + a_koff) * 2;
            ldsm_x4(ah0, ah1, ah2, ah3, sb + SM_XH + aoff);
            ldsm_x4(al0, al1, al2, al3, sb + SM_XL + aoff);
            uint32_t bh[4], bl[4];
            uint32_t boff = (uint32_t)(b_row * QROW + c * 64 + kk + b_koff) * 2;
            ldsm_x4(bh[0], bh[1], bh[2], bh[3], sb + SM_QH + boff);
            ldsm_x4(bl[0], bl[1], bl[2], bl[3], sb + SM_QL + boff);
            // tile 0 (slots 0-7)
            mma_bf16(c0, ah0, ah1, ah2, ah3, bh[0], bh[1]);
            mma_bf16(c0, ah0, ah1, ah2, ah3, bl[0], bl[1]);
            mma_bf16(c0, al0, al1, al2, al3, bh[0], bh[1]);
            // tile 1 (slots 8-15)
            mma_bf16(c1, ah0, ah1, ah2, ah3, bh[2], bh[3]);
            mma_bf16(c1, ah0, ah1, ah2, ah3, bl[2], bl[3]);
            mma_bf16(c1, al0, al1, al2, al3, bh[2], bh[3]);
        }
    }

    // softmax on fragments. thread holds per row r (=lane>>2) and r+8:
    // slots {2c_,2c_+1} (tile0) and {8+2c_,8+2c_+1} (tile1), c_ = lane&3.
    int c_ = lane & 3;
    bool mask15 = (c_ == 3);
#pragma unroll
    for (int half = 0; half < 2; half++) {
        float v0 = acc0[half * 2 + 0] * 0.0625f;
        float v1 = acc0[half * 2 + 1] * 0.0625f;
        float v2 = acc1[half * 2 + 0] * 0.0625f;
        float v3 = mask15 ? -1e30f : acc1[half * 2 + 1] * 0.0625f;
        float mx = fmaxf(fmaxf(v0, v1), fmaxf(v2, v3));
        mx = fmaxf(mx, __shfl_xor_sync(0xffffffffu, mx, 1));
        mx = fmaxf(mx, __shfl_xor_sync(0xffffffffu, mx, 2));
        v0 = __expf(v0 - mx); v1 = __expf(v1 - mx);
        v2 = __expf(v2 - mx); v3 = mask15 ? 0.f : __expf(v3 - mx);
        float sum = v0 + v1 + v2 + v3;
        sum += __shfl_xor_sync(0xffffffffu, sum, 1);
        sum += __shfl_xor_sync(0xffffffffu, sum, 2);
        float inv = 1.0f / sum;
        int n_loc = wid * 16 + (lane >> 2) + half * 8;
        as_[(2 * c_ + 0) * AS2 + n_loc] = v0 * inv;
        as_[(2 * c_ + 1) * AS2 + n_loc] = v1 * inv;
        as_[(8 + 2 * c_) * AS2 + n_loc] = v2 * inv;
        if (!mask15) as_[(9 + 2 * c_) * AS2 + n_loc] = v3 * inv;
    }
    __syncthreads();

    if (final_pass) {
        for (int i = t; i < Kk * CHN; i += 256) {
            int s = i >> 7, n = i & 127;
            attn_out[((size_t)(b * Kk + s)) * Nn + n_glob0 + n] = as_[s * AS2 + n];
        }
        return;
    }

    // partial rowsums (15 threads)
    if (t < Kk) {
        float ps = 0.f;
#pragma unroll 8
        for (int n = 0; n < CHN; n++) ps += as_[t * AS2 + n];
        g_part[(b * Kk + t) * NCH + chunk] = ps;
    }

    // phase 2 (fp32): U_partial[s][d=t] = Σ_n as[s][n]·x̂[n][d]
    float acc[Kk];
#pragma unroll
    for (int s = 0; s < Kk; s++) acc[s] = 0.f;
    const float* xp = g_xln + ((size_t)b * Nn + n_glob0) * Dd + t;
#pragma unroll 2
    for (int n4 = 0; n4 < CHN / 4; n4++) {
        float x0 = xp[(4 * n4 + 0) * Dd];
        float x1 = xp[(4 * n4 + 1) * Dd];
        float x2 = xp[(4 * n4 + 2) * Dd];
        float x3 = xp[(4 * n4 + 3) * Dd];
#pragma unroll
        for (int s = 0; s < Kk; s++) {
            float4 a4 = *(const float4*)(as_ + s * AS2 + 4 * n4);
            acc[s] += a4.x * x0 + a4.y * x1 + a4.z * x2 + a4.w * x3;
        }
    }
#pragma unroll
    for (int s = 0; s < Kk; s++)
        g_updpart[((size_t)chunk * BK_TOT + b * Kk + s) * Dd + t] = acc[s];
}

// ---------------- fused slot update: U-reduce → GRU → MLP → LN → q ----------------
__global__ __launch_bounds__(256) void slot_update_kernel(
    const float* __restrict__ whh, const float* __restrict__ w1,
    const float* __restrict__ w2,
    const float* __restrict__ bih, const float* __restrict__ bhh,
    const float* __restrict__ b1, const float* __restrict__ b2,
    const float* __restrict__ lnm_w, const float* __restrict__ lnm_b,
    const float* __restrict__ lns_w, const float* __restrict__ lns_b) {
    __shared__ float u_s[8][256];
    __shared__ float h_s[8][256];
    __shared__ float a_s[8][256];
    __shared__ float h1_s[8][512];
    __shared__ float inv_s[8];
    int t = threadIdx.x, lane = t & 31, wid = t >> 5;
    int row0 = blockIdx.x * 8;

#pragma unroll
    for (int r = 0; r < 8; r++) h_s[r][t] = g_slots[(size_t)(row0 + r) * Dd + t];
    if (t < 8) {
        float s = 0.f;
#pragma unroll
        for (int c = 0; c < NCH; c++) s += g_part[(row0 + t) * NCH + c];
        inv_s[t] = 1.0f / (s + 1e-8f);
    }
    __syncthreads();
#pragma unroll
    for (int r = 0; r < 8; r++) {
        float a = 0.f;
#pragma unroll
        for (int c = 0; c < NCH; c++)
            a += g_updpart[((size_t)c * BK_TOT + row0 + r) * Dd + t];
        u_s[r][t] = a * inv_s[r];
    }
    __syncthreads();

    float ri[8] = {0}, rh[8] = {0}, zi[8] = {0}, zh[8] = {0}, ni[8] = {0}, nh[8] = {0};
    dot4<64>(ri, &u_s[0][0], 256, g_wiv + (size_t)t * Dd);
    dot4<64>(zi, &u_s[0][0], 256, g_wiv + (size_t)(256 + t) * Dd);
    dot4<64>(ni, &u_s[0][0], 256, g_wiv + (size_t)(512 + t) * Dd);
    dot4<64>(rh, &h_s[0][0], 256, whh + (size_t)t * Dd);
    dot4<64>(zh, &h_s[0][0], 256, whh + (size_t)(256 + t) * Dd);
    dot4<64>(nh, &h_s[0][0], 256, whh + (size_t)(512 + t) * Dd);
    float bir = bih[t], bhr = bhh[t];
    float biz = bih[256 + t], bhz = bhh[256 + t];
    float bin = bih[512 + t], bhn = bhh[512 + t];
    __syncthreads();
#pragma unroll
    for (int r = 0; r < 8; r++) {
        float rg = sigmoidf_(ri[r] + bir + rh[r] + bhr);
        float zg = sigmoidf_(zi[r] + biz + zh[r] + bhz);
        float ng = tanhf(ni[r] + bin + rg * (nh[r] + bhn));
        h_s[r][t] = (1.0f - zg) * ng + zg * h_s[r][t];
    }
    __syncthreads();
    warp_ln_row(&h_s[wid][0], &a_s[wid][0], lnm_w, lnm_b, lane);
    __syncthreads();
    float m0[8] = {0}, m1[8] = {0};
    dot4<64>(m0, &a_s[0][0], 256, w1 + (size_t)t * Dd);
    dot4<64>(m1, &a_s[0][0], 256, w1 + (size_t)(256 + t) * Dd);
    float b1a = b1[t], b1b = b1[256 + t];
#pragma unroll
    for (int r = 0; r < 8; r++) {
        h1_s[r][t] = fmaxf(m0[r] + b1a, 0.f);
        h1_s[r][256 + t] = fmaxf(m1[r] + b1b, 0.f);
    }
    __syncthreads();
    float m2[8] = {0};
    dot4<128>(m2, &h1_s[0][0], 512, w2 + (size_t)t * Hh);
    float b2t = b2[t];
#pragma unroll
    for (int r = 0; r < 8; r++) {
        float ns = h_s[r][t] + m2[r] + b2t;
        g_slots[(size_t)(row0 + r) * Dd + t] = ns;
        a_s[r][t] = ns;
    }
    __syncthreads();
    warp_ln_row(&a_s[wid][0], &u_s[wid][0], lns_w, lns_b, lane);
    __syncthreads();
    float qa[8] = {0};
    dot4<64>(qa, &u_s[0][0], 256, g_wqk + (size_t)t * Dd);
#pragma unroll
    for (int r = 0; r < 8; r++) store_q_hilo(row0 + r, t, qa[r]);
}

__global__ void copy_kernel(const float* __restrict__ src, float* __restrict__ dst, int n) {
    int i = blockIdx.x * 256 + threadIdx.x;
    if (i < n) dst[i] = src[i];
}

// ---------------- host orchestration ----------------
extern "C" void kernel_launch(void* const* d_in, const int* in_sizes, int n_in,
                              void* d_out, int out_size) {
    const float* inputs        = (const float*)d_in[0];
    const float* slot_noise    = (const float*)d_in[1];
    const float* slots_mu      = (const float*)d_in[2];
    const float* slots_logsig  = (const float*)d_in[3];
    const float* Wq            = (const float*)d_in[4];
    const float* Wk            = (const float*)d_in[5];
    const float* Wv            = (const float*)d_in[6];
    const float* w_ih          = (const float*)d_in[7];
    const float* w_hh          = (const float*)d_in[8];
    const float* b_ih          = (const float*)d_in[9];
    const float* b_hh          = (const float*)d_in[10];
    const float* mlp_w1        = (const float*)d_in[11];
    const float* mlp_b1        = (const float*)d_in[12];
    const float* mlp_w2        = (const float*)d_in[13];
    const float* mlp_b2        = (const float*)d_in[14];
    const float* ln_in_w       = (const float*)d_in[15];
    const float* ln_in_b       = (const float*)d_in[16];
    const float* ln_s_w        = (const float*)d_in[17];
    const float* ln_s_b        = (const float*)d_in[18];
    const float* ln_m_w        = (const float*)d_in[19];
    const float* ln_m_b        = (const float*)d_in[20];
    float* out = (float*)d_out;

    float *p_wqk, *p_wiv, *p_slots;
    cudaGetSymbolAddress((void**)&p_wqk, g_wqk);
    cudaGetSymbolAddress((void**)&p_wiv, g_wiv);
    cudaGetSymbolAddress((void**)&p_slots, g_slots);

    cudaFuncSetAttribute(attn_pass_kernel,
                         cudaFuncAttributeMaxDynamicSharedMemorySize, SM_BYTES);

    ln_apply_kernel<<<BN_TOT / 8, dim3(32, 8)>>>(inputs, ln_in_w, ln_in_b);
    atb_kernel<<<dim3(4, 4), 256>>>(Wk, Wq, p_wqk);
    ab_kernel<<<dim3(12, 4), 256>>>(w_ih, Wv, p_wiv);
    slots_init_kernel<<<BK_TOT, 256>>>(slots_mu, slots_logsig, slot_noise);
    slot_lnq_kernel<<<120, 256>>>(ln_s_w, ln_s_b);

    for (int it = 0; it < 3; it++) {
        attn_pass_kernel<<<dim3(NCH, Bb), 256, SM_BYTES>>>(nullptr, 0);
        slot_update_kernel<<<120, 256>>>(w_hh, mlp_w1, mlp_w2, b_ih, b_hh,
                                         mlp_b1, mlp_b2, ln_m_w, ln_m_b, ln_s_w, ln_s_b);
    }

    attn_pass_kernel<<<dim3(NCH, Bb), 256, SM_BYTES>>>(out + BK_TOT * Dd, 1);
    copy_kernel<<<960, 256>>>(p_slots, out, BK_TOT * Dd);
}

// round 13
// speedup vs baseline: 1.0386x; 1.0386x over previous
#include <cuda_runtime.h>
#include <math.h>
#include <stdint.h>

// SlotAttention GB300 — Round 12: R10 base (best) with restructured attn_pass:
// phase 1 = 8 lanes/row, 4 rows/thread (nL=4 coalescing, q-LDS amortized 16x);
// phase 2 = 4 d/thread, 4-way n-split (as_ smem 1 B/MAC, float4 x loads).
// All fp32. Rest identical to R10.

#define Bb 64
#define Nn 4096
#define Dd 256
#define Kk 15
#define Hh 512
#define BN_TOT (Bb * Nn)   // 262144
#define BK_TOT (Bb * Kk)   // 960
#define NCH 16             // n-chunks per batch
#define CHN 256            // n per chunk
#define NSL (NCH * 4)      // update-partial slices (4 n-quarters per chunk)
#define AS_STR 260         // as_ row stride (floats)

// ---------------- scratch ----------------
__device__ float g_xln[(size_t)BN_TOT * Dd];      // 256 MiB
__device__ float g_wqk[Dd * Dd];                  // [e][d] = Σ_j Wk[j,e]·Wq[j,d]
__device__ float g_wiv[3 * Dd * Dd];              // [g][e] = Σ_d w_ih[g,d]·Wv[d,e]
__device__ float g_slots[BK_TOT * Dd];
__device__ float g_q[BK_TOT * Dd];
__device__ float g_part[BK_TOT * NCH];
__device__ float g_updpart[(size_t)NSL * BK_TOT * Dd];  // 63 MB

// ---------------- helpers ----------------
__device__ __forceinline__ float warp_sum(float v) {
#pragma unroll
    for (int o = 16; o > 0; o >>= 1) v += __shfl_xor_sync(0xffffffffu, v, o);
    return v;
}
__device__ __forceinline__ float sigmoidf_(float x) { return 1.0f / (1.0f + __expf(-x)); }

template <int K4>
__device__ __forceinline__ void dot4(float acc[8], const float* S, int srow,
                                     const float* __restrict__ Wrow) {
    const float4* w4 = (const float4*)Wrow;
#pragma unroll 4
    for (int d4 = 0; d4 < K4; d4++) {
        float4 w = w4[d4];
#pragma unroll
        for (int r = 0; r < 8; r++) {
            const float4 sv = *(const float4*)(S + r * srow + d4 * 4);
            acc[r] += sv.x * w.x + sv.y * w.y + sv.z * w.z + sv.w * w.w;
        }
    }
}

__device__ __forceinline__ void warp_ln_row(const float* src, float* dst,
                                            const float* __restrict__ w,
                                            const float* __restrict__ b, int lane) {
    float vals[8];
    float s = 0.f, s2 = 0.f;
#pragma unroll
    for (int k = 0; k < 8; k++) {
        float v = src[lane + 32 * k];
        vals[k] = v; s += v; s2 += v * v;
    }
    s = warp_sum(s); s2 = warp_sum(s2);
    float m = s * (1.0f / 256.0f);
    float rs = rsqrtf(s2 * (1.0f / 256.0f) - m * m + 1e-5f);
#pragma unroll
    for (int k = 0; k < 8; k++) {
        int d = lane + 32 * k;
        dst[d] = (vals[k] - m) * rs * w[d] + b[d];
    }
}

// ---------------- big LN over inputs ----------------
__global__ void ln_apply_kernel(const float* __restrict__ x, float* __restrict__ y,
                                const float* __restrict__ w, const float* __restrict__ bb) {
    int row = blockIdx.x * 8 + threadIdx.y;
    int lane = threadIdx.x;
    warp_ln_row(x + (size_t)row * Dd, y + (size_t)row * Dd, w, bb, lane);
}

// ---------------- precompute: C[e][d] = Σ_j X[j][e]·Y[j][d]  (XᵀY) ----------------
__global__ __launch_bounds__(256) void atb_kernel(const float* __restrict__ X,
                                                  const float* __restrict__ Y,
                                                  float* __restrict__ C) {
    __shared__ float Xs[16][68];
    __shared__ float Ys[16][68];
    int e0 = blockIdx.x * 64, d0 = blockIdx.y * 64;
    int tid = threadIdx.x;
    int row_t = tid >> 4, col_t = tid & 15;
    int jr = tid >> 4, c4 = (tid & 15) << 2;
    float acc[4][4];
#pragma unroll
    for (int i = 0; i < 4; i++)
#pragma unroll
        for (int j = 0; j < 4; j++) acc[i][j] = 0.f;
    for (int jb = 0; jb < 256; jb += 16) {
        float4 xv = *(const float4*)(X + (size_t)(jb + jr) * Dd + e0 + c4);
        Xs[jr][c4 + 0] = xv.x; Xs[jr][c4 + 1] = xv.y;
        Xs[jr][c4 + 2] = xv.z; Xs[jr][c4 + 3] = xv.w;
        float4 yv = *(const float4*)(Y + (size_t)(jb + jr) * Dd + d0 + c4);
        Ys[jr][c4 + 0] = yv.x; Ys[jr][c4 + 1] = yv.y;
        Ys[jr][c4 + 2] = yv.z; Ys[jr][c4 + 3] = yv.w;
        __syncthreads();
#pragma unroll
        for (int k = 0; k < 16; k++)
#pragma unroll
            for (int i = 0; i < 4; i++)
#pragma unroll
                for (int j = 0; j < 4; j++)
                    acc[i][j] += Xs[k][row_t * 4 + i] * Ys[k][col_t * 4 + j];
        __syncthreads();
    }
#pragma unroll
    for (int i = 0; i < 4; i++)
#pragma unroll
        for (int j = 0; j < 4; j++)
            C[(size_t)(e0 + row_t * 4 + i) * Dd + d0 + col_t * 4 + j] = acc[i][j];
}

// ---------------- precompute: C[g][e] = Σ_d A[g][d]·B[d][e]  (A·B) ----------------
__global__ __launch_bounds__(256) void ab_kernel(const float* __restrict__ A,
                                                 const float* __restrict__ B,
                                                 float* __restrict__ C) {
    __shared__ float As[16][68];
    __shared__ float Bs[16][68];
    int g0 = blockIdx.x * 64, e0 = blockIdx.y * 64;
    int tid = threadIdx.x;
    int row_t = tid >> 4, col_t = tid & 15;
    int r = tid >> 2, k4 = (tid & 3) << 2;
    int jr = tid >> 4, c4 = (tid & 15) << 2;
    float acc[4][4];
#pragma unroll
    for (int i = 0; i < 4; i++)
#pragma unroll
        for (int j = 0; j < 4; j++) acc[i][j] = 0.f;
    for (int db = 0; db < 256; db += 16) {
        float4 av = *(const float4*)(A + (size_t)(g0 + r) * Dd + db + k4);
        As[k4 + 0][r] = av.x; As[k4 + 1][r] = av.y;
        As[k4 + 2][r] = av.z; As[k4 + 3][r] = av.w;
        float4 bv = *(const float4*)(B + (size_t)(db + jr) * Dd + e0 + c4);
        Bs[jr][c4 + 0] = bv.x; Bs[jr][c4 + 1] = bv.y;
        Bs[jr][c4 + 2] = bv.z; Bs[jr][c4 + 3] = bv.w;
        __syncthreads();
#pragma unroll
        for (int k = 0; k < 16; k++)
#pragma unroll
            for (int i = 0; i < 4; i++)
#pragma unroll
                for (int j = 0; j < 4; j++)
                    acc[i][j] += As[k][row_t * 4 + i] * Bs[k][col_t * 4 + j];
        __syncthreads();
    }
#pragma unroll
    for (int i = 0; i < 4; i++)
#pragma unroll
        for (int j = 0; j < 4; j++)
            C[(size_t)(g0 + row_t * 4 + i) * Dd + e0 + col_t * 4 + j] = acc[i][j];
}

// ---------------- slots init ----------------
__global__ void slots_init_kernel(const float* __restrict__ mu,
                                  const float* __restrict__ ls,
                                  const float* __restrict__ noise) {
    int i = blockIdx.x * 256 + threadIdx.x;
    int kd = i % (Kk * Dd);
    g_slots[i] = mu[kd] + __expf(ls[kd]) * noise[i];
}

// ---------------- ln_slots + q (before first iteration) ----------------
__global__ __launch_bounds__(256) void slot_lnq_kernel(const float* __restrict__ lns_w,
                                                       const float* __restrict__ lns_b) {
    __shared__ float a_s[8][256];
    int t = threadIdx.x, lane = t & 31, wid = t >> 5;
    int row0 = blockIdx.x * 8;
    warp_ln_row(g_slots + (size_t)(row0 + wid) * Dd, &a_s[wid][0], lns_w, lns_b, lane);
    __syncthreads();
    float qa[8] = {0, 0, 0, 0, 0, 0, 0, 0};
    dot4<64>(qa, &a_s[0][0], 256, g_wqk + (size_t)t * Dd);
#pragma unroll
    for (int r = 0; r < 8; r++) g_q[(size_t)(row0 + r) * Dd + t] = qa[r];
}

// ---------------- fused attention pass ----------------
// grid (NCH, Bb), block 256.
// Phase 1: thread (rg=t>>3, g8=t&7): rows rg*4..rg*4+3 (2 sweeps of 128 rows),
//          d4 = 8i+g8. Warp LDG = 4 full 128B lines. 3-bfly reduce over 8 lanes.
// Phase 2: thread (q4=t&63, nh=t>>6): d = 4q4..4q4+3, n-quarter nh.
__global__ __launch_bounds__(256) void attn_pass_kernel(const float* __restrict__ q,
                                                        const float* __restrict__ xln,
                                                        float* __restrict__ attn_out,
                                                        int final_pass) {
    __shared__ float qs[Kk * Dd];
    __shared__ float as_[Kk * AS_STR];
    int b = blockIdx.y, chunk = blockIdx.x, t = threadIdx.x;
    int g8 = t & 7, rg = t >> 3;

    const float4* qb = (const float4*)(q + (size_t)b * Kk * Dd);
    float4* qs4 = (float4*)qs;
    for (int i = t; i < Kk * 64; i += 256) qs4[i] = qb[i];
    __syncthreads();

    size_t nbase = (size_t)b * Nn + chunk * CHN;
    const float4* xr4 = (const float4*)(xln + nbase * Dd);   // row stride 64 float4

    int s_a = 2 * g8, s_b = 2 * g8 + 1;                      // this lane's slots
#pragma unroll
    for (int sweep = 0; sweep < 2; sweep++) {
        int r0 = sweep * 128 + rg * 4;
        float l[4][Kk];
#pragma unroll
        for (int j = 0; j < 4; j++)
#pragma unroll
            for (int s = 0; s < Kk; s++) l[j][s] = 0.f;
#pragma unroll 2
        for (int i = 0; i < 8; i++) {
            int d4 = 8 * i + g8;
            float4 xv[4];
#pragma unroll
            for (int j = 0; j < 4; j++) xv[j] = xr4[(size_t)(r0 + j) * 64 + d4];
#pragma unroll
            for (int s = 0; s < Kk; s++) {
                float4 qv = qs4[s * 64 + d4];
#pragma unroll
                for (int j = 0; j < 4; j++)
                    l[j][s] += qv.x * xv[j].x + qv.y * xv[j].y +
                               qv.z * xv[j].z + qv.w * xv[j].w;
            }
        }
        // reduce over the 8-lane d-group
#pragma unroll
        for (int j = 0; j < 4; j++)
#pragma unroll
            for (int s = 0; s < Kk; s++) {
                l[j][s] += __shfl_xor_sync(0xffffffffu, l[j][s], 1);
                l[j][s] += __shfl_xor_sync(0xffffffffu, l[j][s], 2);
                l[j][s] += __shfl_xor_sync(0xffffffffu, l[j][s], 4);
            }
        // softmax per row (computed redundantly on all 8 lanes)
#pragma unroll
        for (int j = 0; j < 4; j++) {
            float mx = -1e30f;
#pragma unroll
            for (int s = 0; s < Kk; s++) { l[j][s] *= 0.0625f; mx = fmaxf(mx, l[j][s]); }
            float sum = 0.f;
#pragma unroll
            for (int s = 0; s < Kk; s++) { l[j][s] = __expf(l[j][s] - mx); sum += l[j][s]; }
            float inv = 1.0f / sum;
            as_[s_a * AS_STR + r0 + j] = l[j][s_a] * inv;
            if (s_b < Kk) as_[s_b * AS_STR + r0 + j] = l[j][s_b] * inv;
        }
    }
    __syncthreads();

    if (final_pass) {
        for (int i = t; i < Kk * CHN; i += 256) {
            int s = i >> 8, n = i & 255;
            attn_out[((size_t)(b * Kk + s)) * Nn + chunk * CHN + n] = as_[s * AS_STR + n];
        }
        return;
    }

    // partial rowsums (15 threads)
    if (t < Kk) {
        float ps = 0.f;
#pragma unroll 8
        for (int n = 0; n < CHN; n++) ps += as_[t * AS_STR + n];
        g_part[(b * Kk + t) * NCH + chunk] = ps;
    }

    // phase 2: thread (q4, nh): acc4[s] (float4 over d=4q4..4q4+3) for n-quarter nh
    int q4 = t & 63, nh = t >> 6;
    float4 acc4[Kk];
#pragma unroll
    for (int s = 0; s < Kk; s++) acc4[s] = make_float4(0.f, 0.f, 0.f, 0.f);
    const float4* xp4 = (const float4*)(xln + (nbase + nh * 64) * Dd) + q4;
    const float* asq = as_ + nh * 64;
#pragma unroll 2
    for (int n4 = 0; n4 < 16; n4++) {
        float4 xv[4];
#pragma unroll
        for (int j = 0; j < 4; j++) xv[j] = xp4[(size_t)(4 * n4 + j) * 64];
#pragma unroll
        for (int s = 0; s < Kk; s++) {
            float4 a4 = *(const float4*)(asq + s * AS_STR + 4 * n4);
            acc4[s].x += a4.x * xv[0].x + a4.y * xv[1].x + a4.z * xv[2].x + a4.w * xv[3].x;
            acc4[s].y += a4.x * xv[0].y + a4.y * xv[1].y + a4.z * xv[2].y + a4.w * xv[3].y;
            acc4[s].z += a4.x * xv[0].z + a4.y * xv[1].z + a4.z * xv[2].z + a4.w * xv[3].z;
            acc4[s].w += a4.x * xv[0].w + a4.y * xv[1].w + a4.z * xv[2].w + a4.w * xv[3].w;
        }
    }
    int slice = chunk * 4 + nh;
#pragma unroll
    for (int s = 0; s < Kk; s++)
        *(float4*)(g_updpart + ((size_t)slice * BK_TOT + b * Kk + s) * Dd + 4 * q4) = acc4[s];
}

// ---------------- fused slot update: U-reduce → GRU → MLP → LN → q ----------------
__global__ __launch_bounds__(256) void slot_update_kernel(
    const float* __restrict__ whh, const float* __restrict__ w1,
    const float* __restrict__ w2,
    const float* __restrict__ bih, const float* __restrict__ bhh,
    const float* __restrict__ b1, const float* __restrict__ b2,
    const float* __restrict__ lnm_w, const float* __restrict__ lnm_b,
    const float* __restrict__ lns_w, const float* __restrict__ lns_b) {
    __shared__ float u_s[8][256];
    __shared__ float h_s[8][256];
    __shared__ float a_s[8][256];
    __shared__ float h1_s[8][512];
    __shared__ float inv_s[8];
    int t = threadIdx.x, lane = t & 31, wid = t >> 5;
    int row0 = blockIdx.x * 8;

#pragma unroll
    for (int r = 0; r < 8; r++) h_s[r][t] = g_slots[(size_t)(row0 + r) * Dd + t];
    if (t < 8) {
        float s = 0.f;
#pragma unroll
        for (int c = 0; c < NCH; c++) s += g_part[(row0 + t) * NCH + c];
        inv_s[t] = 1.0f / (s + 1e-8f);
    }
    __syncthreads();
#pragma unroll
    for (int r = 0; r < 8; r++) {
        float a = 0.f;
#pragma unroll 8
        for (int c = 0; c < NSL; c++)
            a += g_updpart[((size_t)c * BK_TOT + row0 + r) * Dd + t];
        u_s[r][t] = a * inv_s[r];
    }
    __syncthreads();

    float ri[8] = {0}, rh[8] = {0}, zi[8] = {0}, zh[8] = {0}, ni[8] = {0}, nh[8] = {0};
    dot4<64>(ri, &u_s[0][0], 256, g_wiv + (size_t)t * Dd);
    dot4<64>(zi, &u_s[0][0], 256, g_wiv + (size_t)(256 + t) * Dd);
    dot4<64>(ni, &u_s[0][0], 256, g_wiv + (size_t)(512 + t) * Dd);
    dot4<64>(rh, &h_s[0][0], 256, whh + (size_t)t * Dd);
    dot4<64>(zh, &h_s[0][0], 256, whh + (size_t)(256 + t) * Dd);
    dot4<64>(nh, &h_s[0][0], 256, whh + (size_t)(512 + t) * Dd);
    float bir = bih[t], bhr = bhh[t];
    float biz = bih[256 + t], bhz = bhh[256 + t];
    float bin = bih[512 + t], bhn = bhh[512 + t];
    __syncthreads();
#pragma unroll
    for (int r = 0; r < 8; r++) {
        float rg = sigmoidf_(ri[r] + bir + rh[r] + bhr);
        float zg = sigmoidf_(zi[r] + biz + zh[r] + bhz);
        float ng = tanhf(ni[r] + bin + rg * (nh[r] + bhn));
        h_s[r][t] = (1.0f - zg) * ng + zg * h_s[r][t];
    }
    __syncthreads();
    warp_ln_row(&h_s[wid][0], &a_s[wid][0], lnm_w, lnm_b, lane);
    __syncthreads();
    float m0[8] = {0}, m1[8] = {0};
    dot4<64>(m0, &a_s[0][0], 256, w1 + (size_t)t * Dd);
    dot4<64>(m1, &a_s[0][0], 256, w1 + (size_t)(256 + t) * Dd);
    float b1a = b1[t], b1b = b1[256 + t];
#pragma unroll
    for (int r = 0; r < 8; r++) {
        h1_s[r][t] = fmaxf(m0[r] + b1a, 0.f);
        h1_s[r][256 + t] = fmaxf(m1[r] + b1b, 0.f);
    }
    __syncthreads();
    float m2[8] = {0};
    dot4<128>(m2, &h1_s[0][0], 512, w2 + (size_t)t * Hh);
    float b2t = b2[t];
#pragma unroll
    for (int r = 0; r < 8; r++) {
        float ns = h_s[r][t] + m2[r] + b2t;
        g_slots[(size_t)(row0 + r) * Dd + t] = ns;
        a_s[r][t] = ns;
    }
    __syncthreads();
    warp_ln_row(&a_s[wid][0], &u_s[wid][0], lns_w, lns_b, lane);
    __syncthreads();
    float qa[8] = {0};
    dot4<64>(qa, &u_s[0][0], 256, g_wqk + (size_t)t * Dd);
#pragma unroll
    for (int r = 0; r < 8; r++) g_q[(size_t)(row0 + r) * Dd + t] = qa[r];
}

__global__ void copy_kernel(const float* __restrict__ src, float* __restrict__ dst, int n) {
    int i = blockIdx.x * 256 + threadIdx.x;
    if (i < n) dst[i] = src[i];
}

// ---------------- host orchestration ----------------
extern "C" void kernel_launch(void* const* d_in, const int* in_sizes, int n_in,
                              void* d_out, int out_size) {
    const float* inputs        = (const float*)d_in[0];
    const float* slot_noise    = (const float*)d_in[1];
    const float* slots_mu      = (const float*)d_in[2];
    const float* slots_logsig  = (const float*)d_in[3];
    const float* Wq            = (const float*)d_in[4];
    const float* Wk            = (const float*)d_in[5];
    const float* Wv            = (const float*)d_in[6];
    const float* w_ih          = (const float*)d_in[7];
    const float* w_hh          = (const float*)d_in[8];
    const float* b_ih          = (const float*)d_in[9];
    const float* b_hh          = (const float*)d_in[10];
    const float* mlp_w1        = (const float*)d_in[11];
    const float* mlp_b1        = (const float*)d_in[12];
    const float* mlp_w2        = (const float*)d_in[13];
    const float* mlp_b2        = (const float*)d_in[14];
    const float* ln_in_w       = (const float*)d_in[15];
    const float* ln_in_b       = (const float*)d_in[16];
    const float* ln_s_w        = (const float*)d_in[17];
    const float* ln_s_b        = (const float*)d_in[18];
    const float* ln_m_w        = (const float*)d_in[19];
    const float* ln_m_b        = (const float*)d_in[20];
    float* out = (float*)d_out;

    float *p_xln, *p_wqk, *p_wiv, *p_q, *p_slots;
    cudaGetSymbolAddress((void**)&p_xln, g_xln);
    cudaGetSymbolAddress((void**)&p_wqk, g_wqk);
    cudaGetSymbolAddress((void**)&p_wiv, g_wiv);
    cudaGetSymbolAddress((void**)&p_q, g_q);
    cudaGetSymbolAddress((void**)&p_slots, g_slots);

    ln_apply_kernel<<<BN_TOT / 8, dim3(32, 8)>>>(inputs, p_xln, ln_in_w, ln_in_b);
    atb_kernel<<<dim3(4, 4), 256>>>(Wk, Wq, p_wqk);
    ab_kernel<<<dim3(12, 4), 256>>>(w_ih, Wv, p_wiv);
    slots_init_kernel<<<BK_TOT, 256>>>(slots_mu, slots_logsig, slot_noise);
    slot_lnq_kernel<<<120, 256>>>(ln_s_w, ln_s_b);

    for (int it = 0; it < 3; it++) {
        attn_pass_kernel<<<dim3(NCH, Bb), 256>>>(p_q, p_xln, nullptr, 0);
        slot_update_kernel<<<120, 256>>>(w_hh, mlp_w1, mlp_w2, b_ih, b_hh,
                                         mlp_b1, mlp_b2, ln_m_w, ln_m_b, ln_s_w, ln_s_b);
    }

    attn_pass_kernel<<<dim3(NCH, Bb), 256>>>(p_q, p_xln, out + BK_TOT * Dd, 1);
    copy_kernel<<<960, 256>>>(p_slots, out, BK_TOT * Dd);
}

// round 14
// speedup vs baseline: 1.0418x; 1.0031x over previous
#include <cuda_runtime.h>
#include <math.h>
#include <stdint.h>

// SlotAttention GB300 — Round 13: R10 (best, 1357us) with inner FMA loops
// converted to packed fma.rn.f32x2 (Blackwell FFMA2, 2 MACs/inst) in
// attn_pass phase 1/2 and slot_update dot4. Structure/mappings unchanged.

#define Bb 64
#define Nn 4096
#define Dd 256
#define Kk 15
#define Hh 512
#define BN_TOT (Bb * Nn)   // 262144
#define BK_TOT (Bb * Kk)   // 960
#define NCH 16             // n-chunks per batch
#define CHN 256            // n per chunk
#define AS_STR 260         // as_ row stride (floats)

typedef unsigned long long u64t;

// ---------------- scratch ----------------
__device__ float g_xln[(size_t)BN_TOT * Dd];      // 256 MiB
__device__ float g_wqk[Dd * Dd];                  // [e][d] = Σ_j Wk[j,e]·Wq[j,d]
__device__ float g_wiv[3 * Dd * Dd];              // [g][e] = Σ_d w_ih[g,d]·Wv[d,e]
__device__ float g_slots[BK_TOT * Dd];
__device__ float g_q[BK_TOT * Dd];
__device__ float g_part[BK_TOT * NCH];
__device__ float g_updpart[(size_t)NCH * BK_TOT * Dd];  // 15.7 MB

// ---------------- packed f32x2 helpers ----------------
__device__ __forceinline__ u64t pack2(float lo, float hi) {
    u64t r; asm("mov.b64 %0, {%1, %2};" : "=l"(r) : "f"(lo), "f"(hi)); return r;
}
__device__ __forceinline__ void unpack2(u64t v, float& lo, float& hi) {
    asm("mov.b64 {%0, %1}, %2;" : "=f"(lo), "=f"(hi) : "l"(v));
}
__device__ __forceinline__ void fma2(u64t& d, u64t a, u64t b) {
    asm("fma.rn.f32x2 %0, %1, %2, %0;" : "+l"(d) : "l"(a), "l"(b));
}

// ---------------- helpers ----------------
__device__ __forceinline__ float warp_sum(float v) {
#pragma unroll
    for (int o = 16; o > 0; o >>= 1) v += __shfl_xor_sync(0xffffffffu, v, o);
    return v;
}
__device__ __forceinline__ float sigmoidf_(float x) { return 1.0f / (1.0f + __expf(-x)); }

// acc[r] += dot(S[r][·], Wrow[·]) via packed f32x2
template <int K4>
__device__ __forceinline__ void dot4(float acc[8], const float* S, int srow,
                                     const float* __restrict__ Wrow) {
    const ulonglong2* w2 = (const ulonglong2*)Wrow;
    u64t a2[8];
#pragma unroll
    for (int r = 0; r < 8; r++) a2[r] = 0ull;
#pragma unroll 4
    for (int d4 = 0; d4 < K4; d4++) {
        ulonglong2 w = w2[d4];
#pragma unroll
        for (int r = 0; r < 8; r++) {
            ulonglong2 sv = *(const ulonglong2*)(S + r * srow + d4 * 4);
            fma2(a2[r], sv.x, w.x);
            fma2(a2[r], sv.y, w.y);
        }
    }
#pragma unroll
    for (int r = 0; r < 8; r++) {
        float lo, hi; unpack2(a2[r], lo, hi);
        acc[r] += lo + hi;
    }
}

__device__ __forceinline__ void warp_ln_row(const float* src, float* dst,
                                            const float* __restrict__ w,
                                            const float* __restrict__ b, int lane) {
    float vals[8];
    float s = 0.f, s2 = 0.f;
#pragma unroll
    for (int k = 0; k < 8; k++) {
        float v = src[lane + 32 * k];
        vals[k] = v; s += v; s2 += v * v;
    }
    s = warp_sum(s); s2 = warp_sum(s2);
    float m = s * (1.0f / 256.0f);
    float rs = rsqrtf(s2 * (1.0f / 256.0f) - m * m + 1e-5f);
#pragma unroll
    for (int k = 0; k < 8; k++) {
        int d = lane + 32 * k;
        dst[d] = (vals[k] - m) * rs * w[d] + b[d];
    }
}

// ---------------- big LN over inputs ----------------
__global__ void ln_apply_kernel(const float* __restrict__ x, float* __restrict__ y,
                                const float* __restrict__ w, const float* __restrict__ bb) {
    int row = blockIdx.x * 8 + threadIdx.y;
    int lane = threadIdx.x;
    warp_ln_row(x + (size_t)row * Dd, y + (size_t)row * Dd, w, bb, lane);
}

// ---------------- precompute: C[e][d] = Σ_j X[j][e]·Y[j][d]  (XᵀY) ----------------
__global__ __launch_bounds__(256) void atb_kernel(const float* __restrict__ X,
                                                  const float* __restrict__ Y,
                                                  float* __restrict__ C) {
    __shared__ float Xs[16][68];
    __shared__ float Ys[16][68];
    int e0 = blockIdx.x * 64, d0 = blockIdx.y * 64;
    int tid = threadIdx.x;
    int row_t = tid >> 4, col_t = tid & 15;
    int jr = tid >> 4, c4 = (tid & 15) << 2;
    float acc[4][4];
#pragma unroll
    for (int i = 0; i < 4; i++)
#pragma unroll
        for (int j = 0; j < 4; j++) acc[i][j] = 0.f;
    for (int jb = 0; jb < 256; jb += 16) {
        float4 xv = *(const float4*)(X + (size_t)(jb + jr) * Dd + e0 + c4);
        Xs[jr][c4 + 0] = xv.x; Xs[jr][c4 + 1] = xv.y;
        Xs[jr][c4 + 2] = xv.z; Xs[jr][c4 + 3] = xv.w;
        float4 yv = *(const float4*)(Y + (size_t)(jb + jr) * Dd + d0 + c4);
        Ys[jr][c4 + 0] = yv.x; Ys[jr][c4 + 1] = yv.y;
        Ys[jr][c4 + 2] = yv.z; Ys[jr][c4 + 3] = yv.w;
        __syncthreads();
#pragma unroll
        for (int k = 0; k < 16; k++)
#pragma unroll
            for (int i = 0; i < 4; i++)
#pragma unroll
                for (int j = 0; j < 4; j++)
                    acc[i][j] += Xs[k][row_t * 4 + i] * Ys[k][col_t * 4 + j];
        __syncthreads();
    }
#pragma unroll
    for (int i = 0; i < 4; i++)
#pragma unroll
        for (int j = 0; j < 4; j++)
            C[(size_t)(e0 + row_t * 4 + i) * Dd + d0 + col_t * 4 + j] = acc[i][j];
}

// ---------------- precompute: C[g][e] = Σ_d A[g][d]·B[d][e]  (A·B) ----------------
__global__ __launch_bounds__(256) void ab_kernel(const float* __restrict__ A,
                                                 const float* __restrict__ B,
                                                 float* __restrict__ C) {
    __shared__ float As[16][68];
    __shared__ float Bs[16][68];
    int g0 = blockIdx.x * 64, e0 = blockIdx.y * 64;
    int tid = threadIdx.x;
    int row_t = tid >> 4, col_t = tid & 15;
    int r = tid >> 2, k4 = (tid & 3) << 2;
    int jr = tid >> 4, c4 = (tid & 15) << 2;
    float acc[4][4];
#pragma unroll
    for (int i = 0; i < 4; i++)
#pragma unroll
        for (int j = 0; j < 4; j++) acc[i][j] = 0.f;
    for (int db = 0; db < 256; db += 16) {
        float4 av = *(const float4*)(A + (size_t)(g0 + r) * Dd + db + k4);
        As[k4 + 0][r] = av.x; As[k4 + 1][r] = av.y;
        As[k4 + 2][r] = av.z; As[k4 + 3][r] = av.w;
        float4 bv = *(const float4*)(B + (size_t)(db + jr) * Dd + e0 + c4);
        Bs[jr][c4 + 0] = bv.x; Bs[jr][c4 + 1] = bv.y;
        Bs[jr][c4 + 2] = bv.z; Bs[jr][c4 + 3] = bv.w;
        __syncthreads();
#pragma unroll
        for (int k = 0; k < 16; k++)
#pragma unroll
            for (int i = 0; i < 4; i++)
#pragma unroll
                for (int j = 0; j < 4; j++)
                    acc[i][j] += As[k][row_t * 4 + i] * Bs[k][col_t * 4 + j];
        __syncthreads();
    }
#pragma unroll
    for (int i = 0; i < 4; i++)
#pragma unroll
        for (int j = 0; j < 4; j++)
            C[(size_t)(g0 + row_t * 4 + i) * Dd + e0 + col_t * 4 + j] = acc[i][j];
}

// ---------------- slots init ----------------
__global__ void slots_init_kernel(const float* __restrict__ mu,
                                  const float* __restrict__ ls,
                                  const float* __restrict__ noise) {
    int i = blockIdx.x * 256 + threadIdx.x;
    int kd = i % (Kk * Dd);
    g_slots[i] = mu[kd] + __expf(ls[kd]) * noise[i];
}

// ---------------- ln_slots + q (before first iteration) ----------------
__global__ __launch_bounds__(256) void slot_lnq_kernel(const float* __restrict__ lns_w,
                                                       const float* __restrict__ lns_b) {
    __shared__ float a_s[8][256];
    int t = threadIdx.x, lane = t & 31, wid = t >> 5;
    int row0 = blockIdx.x * 8;
    warp_ln_row(g_slots + (size_t)(row0 + wid) * Dd, &a_s[wid][0], lns_w, lns_b, lane);
    __syncthreads();
    float qa[8] = {0, 0, 0, 0, 0, 0, 0, 0};
    dot4<64>(qa, &a_s[0][0], 256, g_wqk + (size_t)t * Dd);
#pragma unroll
    for (int r = 0; r < 8; r++) g_q[(size_t)(row0 + r) * Dd + t] = qa[r];
}

// ---------------- fused attention pass (R10 mapping, f32x2 math) -------
// grid (NCH, Bb), block 256. Phase 1: 4 stripes of 64 n; thread (nrel, g)
// accumulates d4 ≡ g (mod 4), bfly-reduce over lanes 1,2. Phase 2: thread=d.
__global__ __launch_bounds__(256) void attn_pass_kernel(const float* __restrict__ q,
                                                        const float* __restrict__ xln,
                                                        float* __restrict__ attn_out,
                                                        int final_pass) {
    __shared__ float qs[Kk * Dd];
    __shared__ float as_[Kk * AS_STR];
    int b = blockIdx.y, chunk = blockIdx.x, t = threadIdx.x;
    int g = t & 3, nrel = t >> 2;

    const float4* qb = (const float4*)(q + (size_t)b * Kk * Dd);
    float4* qs4 = (float4*)qs;
    for (int i = t; i < Kk * 64; i += 256) qs4[i] = qb[i];
    __syncthreads();
    const ulonglong2* qs2 = (const ulonglong2*)qs;

    size_t nbase = (size_t)b * Nn + chunk * CHN;

#pragma unroll
    for (int stripe = 0; stripe < 4; stripe++) {
        int n_loc = stripe * 64 + nrel;
        const ulonglong2* xr = (const ulonglong2*)(xln + (nbase + n_loc) * Dd);
        u64t l2[Kk];
#pragma unroll
        for (int s = 0; s < Kk; s++) l2[s] = 0ull;
#pragma unroll 4
        for (int i = 0; i < 16; i++) {
            int d4 = 4 * i + g;                  // lane g covers d4 ≡ g (mod 4)
            ulonglong2 xv = xr[d4];
#pragma unroll
            for (int s = 0; s < Kk; s++) {
                ulonglong2 qv = qs2[s * 64 + d4];
                fma2(l2[s], qv.x, xv.x);
                fma2(l2[s], qv.y, xv.y);
            }
        }
        float l[Kk];
#pragma unroll
        for (int s = 0; s < Kk; s++) {
            float lo, hi; unpack2(l2[s], lo, hi);
            l[s] = lo + hi;
            l[s] += __shfl_xor_sync(0xffffffffu, l[s], 1);
            l[s] += __shfl_xor_sync(0xffffffffu, l[s], 2);
        }
        float mx = -1e30f;
#pragma unroll
        for (int s = 0; s < Kk; s++) { l[s] *= 0.0625f; mx = fmaxf(mx, l[s]); }
        float sum = 0.f;
#pragma unroll
        for (int s = 0; s < Kk; s++) { l[s] = __expf(l[s] - mx); sum += l[s]; }
        float inv = 1.0f / sum;
#pragma unroll
        for (int s = g; s < Kk; s += 4)
            as_[s * AS_STR + n_loc] = l[s] * inv;
    }
    __syncthreads();

    if (final_pass) {
        for (int i = t; i < Kk * CHN; i += 256) {
            int s = i >> 8, n = i & 255;
            attn_out[((size_t)(b * Kk + s)) * Nn + chunk * CHN + n] = as_[s * AS_STR + n];
        }
        return;
    }

    // partial rowsums (15 threads)
    if (t < Kk) {
        float ps = 0.f;
#pragma unroll 8
        for (int n = 0; n < CHN; n++) ps += as_[t * AS_STR + n];
        g_part[(b * Kk + t) * NCH + chunk] = ps;
    }

    // phase 2 (f32x2): U_partial[s][d=t] = Σ_n as[s][n]·x̂[n][d]
    u64t acc2[Kk];
#pragma unroll
    for (int s = 0; s < Kk; s++) acc2[s] = 0ull;
    const float* xp = xln + nbase * Dd + t;
#pragma unroll 2
    for (int n4 = 0; n4 < CHN / 4; n4++) {
        float x0 = xp[(4 * n4 + 0) * Dd];
        float x1 = xp[(4 * n4 + 1) * Dd];
        float x2 = xp[(4 * n4 + 2) * Dd];
        float x3 = xp[(4 * n4 + 3) * Dd];
        u64t x01 = pack2(x0, x1), x23 = pack2(x2, x3);
#pragma unroll
        for (int s = 0; s < Kk; s++) {
            ulonglong2 a2v = *(const ulonglong2*)(as_ + s * AS_STR + 4 * n4);
            fma2(acc2[s], a2v.x, x01);
            fma2(acc2[s], a2v.y, x23);
        }
    }
#pragma unroll
    for (int s = 0; s < Kk; s++) {
        float lo, hi; unpack2(acc2[s], lo, hi);
        g_updpart[((size_t)chunk * BK_TOT + b * Kk + s) * Dd + t] = lo + hi;
    }
}

// ---------------- fused slot update: U-reduce → GRU → MLP → LN → q ----------------
__global__ __launch_bounds__(256) void slot_update_kernel(
    const float* __restrict__ whh, const float* __restrict__ w1,
    const float* __restrict__ w2,
    const float* __restrict__ bih, const float* __restrict__ bhh,
    const float* __restrict__ b1, const float* __restrict__ b2,
    const float* __restrict__ lnm_w, const float* __restrict__ lnm_b,
    const float* __restrict__ lns_w, const float* __restrict__ lns_b) {
    __shared__ float u_s[8][256];
    __shared__ float h_s[8][256];
    __shared__ float a_s[8][256];
    __shared__ float h1_s[8][512];
    __shared__ float inv_s[8];
    int t = threadIdx.x, lane = t & 31, wid = t >> 5;
    int row0 = blockIdx.x * 8;

#pragma unroll
    for (int r = 0; r < 8; r++) h_s[r][t] = g_slots[(size_t)(row0 + r) * Dd + t];
    if (t < 8) {
        float s = 0.f;
#pragma unroll
        for (int c = 0; c < NCH; c++) s += g_part[(row0 + t) * NCH + c];
        inv_s[t] = 1.0f / (s + 1e-8f);
    }
    __syncthreads();
#pragma unroll
    for (int r = 0; r < 8; r++) {
        float a = 0.f;
#pragma unroll
        for (int c = 0; c < NCH; c++)
            a += g_updpart[((size_t)c * BK_TOT + row0 + r) * Dd + t];
        u_s[r][t] = a * inv_s[r];
    }
    __syncthreads();

    float ri[8] = {0}, rh[8] = {0}, zi[8] = {0}, zh[8] = {0}, ni[8] = {0}, nh[8] = {0};
    dot4<64>(ri, &u_s[0][0], 256, g_wiv + (size_t)t * Dd);
    dot4<64>(zi, &u_s[0][0], 256, g_wiv + (size_t)(256 + t) * Dd);
    dot4<64>(ni, &u_s[0][0], 256, g_wiv + (size_t)(512 + t) * Dd);
    dot4<64>(rh, &h_s[0][0], 256, whh + (size_t)t * Dd);
    dot4<64>(zh, &h_s[0][0], 256, whh + (size_t)(256 + t) * Dd);
    dot4<64>(nh, &h_s[0][0], 256, whh + (size_t)(512 + t) * Dd);
    float bir = bih[t], bhr = bhh[t];
    float biz = bih[256 + t], bhz = bhh[256 + t];
    float bin = bih[512 + t], bhn = bhh[512 + t];
    __syncthreads();
#pragma unroll
    for (int r = 0; r < 8; r++) {
        float rg = sigmoidf_(ri[r] + bir + rh[r] + bhr);
        float zg = sigmoidf_(zi[r] + biz + zh[r] + bhz);
        float ng = tanhf(ni[r] + bin + rg * (nh[r] + bhn));
        h_s[r][t] = (1.0f - zg) * ng + zg * h_s[r][t];
    }
    __syncthreads();
    warp_ln_row(&h_s[wid][0], &a_s[wid][0], lnm_w, lnm_b, lane);
    __syncthreads();
    float m0[8] = {0}, m1[8] = {0};
    dot4<64>(m0, &a_s[0][0], 256, w1 + (size_t)t * Dd);
    dot4<64>(m1, &a_s[0][0], 256, w1 + (size_t)(256 + t) * Dd);
    float b1a = b1[t], b1b = b1[256 + t];
#pragma unroll
    for (int r = 0; r < 8; r++) {
        h1_s[r][t] = fmaxf(m0[r] + b1a, 0.f);
        h1_s[r][256 + t] = fmaxf(m1[r] + b1b, 0.f);
    }
    __syncthreads();
    float m2[8] = {0};
    dot4<128>(m2, &h1_s[0][0], 512, w2 + (size_t)t * Hh);
    float b2t = b2[t];
#pragma unroll
    for (int r = 0; r < 8; r++) {
        float ns = h_s[r][t] + m2[r] + b2t;
        g_slots[(size_t)(row0 + r) * Dd + t] = ns;
        a_s[r][t] = ns;
    }
    __syncthreads();
    warp_ln_row(&a_s[wid][0], &u_s[wid][0], lns_w, lns_b, lane);
    __syncthreads();
    float qa[8] = {0};
    dot4<64>(qa, &u_s[0][0], 256, g_wqk + (size_t)t * Dd);
#pragma unroll
    for (int r = 0; r < 8; r++) g_q[(size_t)(row0 + r) * Dd + t] = qa[r];
}

__global__ void copy_kernel(const float* __restrict__ src, float* __restrict__ dst, int n) {
    int i = blockIdx.x * 256 + threadIdx.x;
    if (i < n) dst[i] = src[i];
}

// ---------------- host orchestration ----------------
extern "C" void kernel_launch(void* const* d_in, const int* in_sizes, int n_in,
                              void* d_out, int out_size) {
    const float* inputs        = (const float*)d_in[0];
    const float* slot_noise    = (const float*)d_in[1];
    const float* slots_mu      = (const float*)d_in[2];
    const float* slots_logsig  = (const float*)d_in[3];
    const float* Wq            = (const float*)d_in[4];
    const float* Wk            = (const float*)d_in[5];
    const float* Wv            = (const float*)d_in[6];
    const float* w_ih          = (const float*)d_in[7];
    const float* w_hh          = (const float*)d_in[8];
    const float* b_ih          = (const float*)d_in[9];
    const float* b_hh          = (const float*)d_in[10];
    const float* mlp_w1        = (const float*)d_in[11];
    const float* mlp_b1        = (const float*)d_in[12];
    const float* mlp_w2        = (const float*)d_in[13];
    const float* mlp_b2        = (const float*)d_in[14];
    const float* ln_in_w       = (const float*)d_in[15];
    const float* ln_in_b       = (const float*)d_in[16];
    const float* ln_s_w        = (const float*)d_in[17];
    const float* ln_s_b        = (const float*)d_in[18];
    const float* ln_m_w        = (const float*)d_in[19];
    const float* ln_m_b        = (const float*)d_in[20];
    float* out = (float*)d_out;

    float *p_xln, *p_wqk, *p_wiv, *p_q, *p_slots;
    cudaGetSymbolAddress((void**)&p_xln, g_xln);
    cudaGetSymbolAddress((void**)&p_wqk, g_wqk);
    cudaGetSymbolAddress((void**)&p_wiv, g_wiv);
    cudaGetSymbolAddress((void**)&p_q, g_q);
    cudaGetSymbolAddress((void**)&p_slots, g_slots);

    ln_apply_kernel<<<BN_TOT / 8, dim3(32, 8)>>>(inputs, p_xln, ln_in_w, ln_in_b);
    atb_kernel<<<dim3(4, 4), 256>>>(Wk, Wq, p_wqk);
    ab_kernel<<<dim3(12, 4), 256>>>(w_ih, Wv, p_wiv);
    slots_init_kernel<<<BK_TOT, 256>>>(slots_mu, slots_logsig, slot_noise);
    slot_lnq_kernel<<<120, 256>>>(ln_s_w, ln_s_b);

    for (int it = 0; it < 3; it++) {
        attn_pass_kernel<<<dim3(NCH, Bb), 256>>>(p_q, p_xln, nullptr, 0);
        slot_update_kernel<<<120, 256>>>(w_hh, mlp_w1, mlp_w2, b_ih, b_hh,
                                         mlp_b1, mlp_b2, ln_m_w, ln_m_b, ln_s_w, ln_s_b);
    }

    attn_pass_kernel<<<dim3(NCH, Bb), 256>>>(p_q, p_xln, out + BK_TOT * Dd, 1);
    copy_kernel<<<960, 256>>>(p_slots, out, BK_TOT * Dd);
}

// round 15
// speedup vs baseline: 1.3757x; 1.3205x over previous
#include <cuda_runtime.h>
#include <cuda_bf16.h>
#include <math.h>
#include <stdint.h>

// SlotAttention GB300 — Round 14: single fp32 x̂ array (R10 memory behavior)
// + HMMA phase-1 logits with ON-THE-FLY bf16 hi/lo conversion during smem
// staging (fixes R11's extra-DRAM failure). Phase 2 & slot chain = R10 exact.

#define Bb 64
#define Nn 4096
#define Dd 256
#define Kk 15
#define Hh 512
#define BN_TOT (Bb * Nn)   // 262144
#define BK_TOT (Bb * Kk)   // 960
#define NCH 32             // n-chunks per batch
#define CHN 128            // n per chunk (HMMA tile M)
#define SROW 72            // x̂ smem row stride (bf16)
#define QROW 264           // q smem row stride (bf16)
#define AS2 132            // attn smem row stride (floats)

// dynamic smem byte offsets for attn_pass
#define SM_XH 0
#define SM_XL 18432
#define SM_QH 36864
#define SM_QL 45312
#define SM_AS 53760
#define SM_BYTES 61680

// ---------------- scratch ----------------
__device__ float g_xln[(size_t)BN_TOT * Dd];      // 256 MiB (ONLY x̂ copy)
__device__ float g_wqk[Dd * Dd];
__device__ float g_wiv[3 * Dd * Dd];
__device__ float g_slots[BK_TOT * Dd];
__device__ float g_q[BK_TOT * Dd];
__device__ float g_part[BK_TOT * NCH];
__device__ float g_updpart[(size_t)NCH * BK_TOT * Dd];  // 31.5 MB

// ---------------- helpers ----------------
__device__ __forceinline__ float warp_sum(float v) {
#pragma unroll
    for (int o = 16; o > 0; o >>= 1) v += __shfl_xor_sync(0xffffffffu, v, o);
    return v;
}
__device__ __forceinline__ float sigmoidf_(float x) { return 1.0f / (1.0f + __expf(-x)); }

__device__ __forceinline__ uint32_t smem_u32(const void* p) {
    uint32_t a;
    asm("{ .reg .u64 t; cvta.to.shared.u64 t, %1; cvt.u32.u64 %0, t; }" : "=r"(a) : "l"(p));
    return a;
}
__device__ __forceinline__ void ldsm_x4(uint32_t& r0, uint32_t& r1, uint32_t& r2, uint32_t& r3,
                                        uint32_t addr) {
    asm volatile("ldmatrix.sync.aligned.m8n8.x4.shared.b16 {%0,%1,%2,%3}, [%4];"
                 : "=r"(r0), "=r"(r1), "=r"(r2), "=r"(r3) : "r"(addr));
}
__device__ __forceinline__ void mma_bf16(float* c, uint32_t a0, uint32_t a1, uint32_t a2,
                                         uint32_t a3, uint32_t b0, uint32_t b1) {
    asm volatile(
        "mma.sync.aligned.m16n8k16.row.col.f32.bf16.bf16.f32 "
        "{%0,%1,%2,%3}, {%4,%5,%6,%7}, {%8,%9}, {%0,%1,%2,%3};"
        : "+f"(c[0]), "+f"(c[1]), "+f"(c[2]), "+f"(c[3])
        : "r"(a0), "r"(a1), "r"(a2), "r"(a3), "r"(b0), "r"(b1));
}

// split a float4 into packed hi (bf16x2 pair) and lo
__device__ __forceinline__ void split4(float4 v, uint2& hval, uint2& lval) {
    __nv_bfloat16 hx = __float2bfloat16(v.x), hy = __float2bfloat16(v.y);
    __nv_bfloat16 hz = __float2bfloat16(v.z), hw = __float2bfloat16(v.w);
    __nv_bfloat16 lx = __float2bfloat16(v.x - __bfloat162float(hx));
    __nv_bfloat16 ly = __float2bfloat16(v.y - __bfloat162float(hy));
    __nv_bfloat16 lz = __float2bfloat16(v.z - __bfloat162float(hz));
    __nv_bfloat16 lw = __float2bfloat16(v.w - __bfloat162float(hw));
    __nv_bfloat162 h01 = {hx, hy}, h23 = {hz, hw};
    __nv_bfloat162 l01 = {lx, ly}, l23 = {lz, lw};
    hval.x = *(uint32_t*)&h01; hval.y = *(uint32_t*)&h23;
    lval.x = *(uint32_t*)&l01; lval.y = *(uint32_t*)&l23;
}

template <int K4>
__device__ __forceinline__ void dot4(float acc[8], const float* S, int srow,
                                     const float* __restrict__ Wrow) {
    const float4* w4 = (const float4*)Wrow;
#pragma unroll 4
    for (int d4 = 0; d4 < K4; d4++) {
        float4 w = w4[d4];
#pragma unroll
        for (int r = 0; r < 8; r++) {
            const float4 sv = *(const float4*)(S + r * srow + d4 * 4);
            acc[r] += sv.x * w.x + sv.y * w.y + sv.z * w.z + sv.w * w.w;
        }
    }
}

__device__ __forceinline__ void warp_ln_row(const float* src, float* dst,
                                            const float* __restrict__ w,
                                            const float* __restrict__ b, int lane) {
    float vals[8];
    float s = 0.f, s2 = 0.f;
#pragma unroll
    for (int k = 0; k < 8; k++) {
        float v = src[lane + 32 * k];
        vals[k] = v; s += v; s2 += v * v;
    }
    s = warp_sum(s); s2 = warp_sum(s2);
    float m = s * (1.0f / 256.0f);
    float rs = rsqrtf(s2 * (1.0f / 256.0f) - m * m + 1e-5f);
#pragma unroll
    for (int k = 0; k < 8; k++) {
        int d = lane + 32 * k;
        dst[d] = (vals[k] - m) * rs * w[d] + b[d];
    }
}

// ---------------- big LN over inputs (fp32 only) ----------------
__global__ void ln_apply_kernel(const float* __restrict__ x, float* __restrict__ y,
                                const float* __restrict__ w, const float* __restrict__ bb) {
    int row = blockIdx.x * 8 + threadIdx.y;
    int lane = threadIdx.x;
    warp_ln_row(x + (size_t)row * Dd, y + (size_t)row * Dd, w, bb, lane);
}

// ---------------- precompute: C[e][d] = Σ_j X[j][e]·Y[j][d]  (XᵀY) ----------------
__global__ __launch_bounds__(256) void atb_kernel(const float* __restrict__ X,
                                                  const float* __restrict__ Y,
                                                  float* __restrict__ C) {
    __shared__ float Xs[16][68];
    __shared__ float Ys[16][68];
    int e0 = blockIdx.x * 64, d0 = blockIdx.y * 64;
    int tid = threadIdx.x;
    int row_t = tid >> 4, col_t = tid & 15;
    int jr = tid >> 4, c4 = (tid & 15) << 2;
    float acc[4][4];
#pragma unroll
    for (int i = 0; i < 4; i++)
#pragma unroll
        for (int j = 0; j < 4; j++) acc[i][j] = 0.f;
    for (int jb = 0; jb < 256; jb += 16) {
        float4 xv = *(const float4*)(X + (size_t)(jb + jr) * Dd + e0 + c4);
        Xs[jr][c4 + 0] = xv.x; Xs[jr][c4 + 1] = xv.y;
        Xs[jr][c4 + 2] = xv.z; Xs[jr][c4 + 3] = xv.w;
        float4 yv = *(const float4*)(Y + (size_t)(jb + jr) * Dd + d0 + c4);
        Ys[jr][c4 + 0] = yv.x; Ys[jr][c4 + 1] = yv.y;
        Ys[jr][c4 + 2] = yv.z; Ys[jr][c4 + 3] = yv.w;
        __syncthreads();
#pragma unroll
        for (int k = 0; k < 16; k++)
#pragma unroll
            for (int i = 0; i < 4; i++)
#pragma unroll
                for (int j = 0; j < 4; j++)
                    acc[i][j] += Xs[k][row_t * 4 + i] * Ys[k][col_t * 4 + j];
        __syncthreads();
    }
#pragma unroll
    for (int i = 0; i < 4; i++)
#pragma unroll
        for (int j = 0; j < 4; j++)
            C[(size_t)(e0 + row_t * 4 + i) * Dd + d0 + col_t * 4 + j] = acc[i][j];
}

// ---------------- precompute: C[g][e] = Σ_d A[g][d]·B[d][e]  (A·B) ----------------
__global__ __launch_bounds__(256) void ab_kernel(const float* __restrict__ A,
                                                 const float* __restrict__ B,
                                                 float* __restrict__ C) {
    __shared__ float As[16][68];
    __shared__ float Bs[16][68];
    int g0 = blockIdx.x * 64, e0 = blockIdx.y * 64;
    int tid = threadIdx.x;
    int row_t = tid >> 4, col_t = tid & 15;
    int r = tid >> 2, k4 = (tid & 3) << 2;
    int jr = tid >> 4, c4 = (tid & 15) << 2;
    float acc[4][4];
#pragma unroll
    for (int i = 0; i < 4; i++)
#pragma unroll
        for (int j = 0; j < 4; j++) acc[i][j] = 0.f;
    for (int db = 0; db < 256; db += 16) {
        float4 av = *(const float4*)(A + (size_t)(g0 + r) * Dd + db + k4);
        As[k4 + 0][r] = av.x; As[k4 + 1][r] = av.y;
        As[k4 + 2][r] = av.z; As[k4 + 3][r] = av.w;
        float4 bv = *(const float4*)(B + (size_t)(db + jr) * Dd + e0 + c4);
        Bs[jr][c4 + 0] = bv.x; Bs[jr][c4 + 1] = bv.y;
        Bs[jr][c4 + 2] = bv.z; Bs[jr][c4 + 3] = bv.w;
        __syncthreads();
#pragma unroll
        for (int k = 0; k < 16; k++)
#pragma unroll
            for (int i = 0; i < 4; i++)
#pragma unroll
                for (int j = 0; j < 4; j++)
                    acc[i][j] += As[k][row_t * 4 + i] * Bs[k][col_t * 4 + j];
        __syncthreads();
    }
#pragma unroll
    for (int i = 0; i < 4; i++)
#pragma unroll
        for (int j = 0; j < 4; j++)
            C[(size_t)(g0 + row_t * 4 + i) * Dd + e0 + col_t * 4 + j] = acc[i][j];
}

// ---------------- slots init ----------------
__global__ void slots_init_kernel(const float* __restrict__ mu,
                                  const float* __restrict__ ls,
                                  const float* __restrict__ noise) {
    int i = blockIdx.x * 256 + threadIdx.x;
    int kd = i % (Kk * Dd);
    g_slots[i] = mu[kd] + __expf(ls[kd]) * noise[i];
}

// ---------------- ln_slots + q (before first iteration) ----------------
__global__ __launch_bounds__(256) void slot_lnq_kernel(const float* __restrict__ lns_w,
                                                       const float* __restrict__ lns_b) {
    __shared__ float a_s[8][256];
    int t = threadIdx.x, lane = t & 31, wid = t >> 5;
    int row0 = blockIdx.x * 8;
    warp_ln_row(g_slots + (size_t)(row0 + wid) * Dd, &a_s[wid][0], lns_w, lns_b, lane);
    __syncthreads();
    float qa[8] = {0, 0, 0, 0, 0, 0, 0, 0};
    dot4<64>(qa, &a_s[0][0], 256, g_wqk + (size_t)t * Dd);
#pragma unroll
    for (int r = 0; r < 8; r++) g_q[(size_t)(row0 + r) * Dd + t] = qa[r];
}

// ---------------- fused attention pass: HMMA phase 1 (on-the-fly bf16 split)
// grid (NCH, Bb), block 256 (8 warps; warp w owns n-rows w*16..w*16+15).
__global__ __launch_bounds__(256) void attn_pass_kernel(const float* __restrict__ q,
                                                        const float* __restrict__ xln,
                                                        float* __restrict__ attn_out,
                                                        int final_pass) {
    extern __shared__ char smc[];
    uint32_t sb = smem_u32(smc);
    float* as_ = (float*)(smc + SM_AS);
    int b = blockIdx.y, chunk = blockIdx.x, t = threadIdx.x;
    int wid = t >> 5, lane = t & 31;

    // stage q (fp32 → hi/lo bf16): 16 rows x 256 d (row 15 zero), stride QROW
    {
        const float4* q4p = (const float4*)(q + (size_t)b * Kk * Dd);
        float4 z4 = make_float4(0.f, 0.f, 0.f, 0.f);
#pragma unroll
        for (int i = t; i < 16 * 64; i += 256) {
            int row = i >> 6, grp = i & 63;            // grp: 4 d per float4
            float4 v = (row < Kk) ? q4p[row * 64 + grp] : z4;
            uint2 hv, lv;
            split4(v, hv, lv);
            int so = (row * QROW + grp * 4) * 2;
            *(uint2*)(smc + SM_QH + so) = hv;
            *(uint2*)(smc + SM_QL + so) = lv;
        }
    }

    int n_glob0 = chunk * CHN;
    int a_row = wid * 16 + (lane & 15);
    int a_koff = (lane >> 4) << 3;
    int b_row = (lane & 7) + ((lane >> 4) << 3);
    int b_koff = ((lane >> 3) & 1) << 3;

    float acc0[8], acc1[8];
#pragma unroll
    for (int i = 0; i < 8; i++) { acc0[i] = 0.f; acc1[i] = 0.f; }

    for (int c = 0; c < 4; c++) {                      // k-chunks of 64 d
        __syncthreads();
        // stage x̂ (fp32 → hi/lo): 128 rows x 64 d, stride SROW
        const float4* xg = (const float4*)(xln + ((size_t)b * Nn + n_glob0) * Dd + c * 64);
#pragma unroll
        for (int i = t; i < 128 * 16; i += 256) {
            int row = i >> 4, grp = i & 15;
            float4 v = xg[(size_t)row * 64 + grp];
            uint2 hv, lv;
            split4(v, hv, lv);
            int so = (row * SROW + grp * 4) * 2;
            *(uint2*)(smc + SM_XH + so) = hv;
            *(uint2*)(smc + SM_XL + so) = lv;
        }
        __syncthreads();
#pragma unroll
        for (int ks = 0; ks < 4; ks++) {
            int kk = ks * 16;
            uint32_t ah0, ah1, ah2, ah3, al0, al1, al2, al3;
            uint32_t aoff = (uint32_t)(a_row * SROW + kk + a_koff) * 2;
            ldsm_x4(ah0, ah1, ah2, ah3, sb + SM_XH + aoff);
            ldsm_x4(al0, al1, al2, al3, sb + SM_XL + aoff);
            uint32_t bh[4], bl[4];
            uint32_t boff = (uint32_t)(b_row * QROW + c * 64 + kk + b_koff) * 2;
            ldsm_x4(bh[0], bh[1], bh[2], bh[3], sb + SM_QH + boff);
            ldsm_x4(bl[0], bl[1], bl[2], bl[3], sb + SM_QL + boff);
            mma_bf16(acc0, ah0, ah1, ah2, ah3, bh[0], bh[1]);
            mma_bf16(acc0, ah0, ah1, ah2, ah3, bl[0], bl[1]);
            mma_bf16(acc0, al0, al1, al2, al3, bh[0], bh[1]);
            mma_bf16(acc1, ah0, ah1, ah2, ah3, bh[2], bh[3]);
            mma_bf16(acc1, ah0, ah1, ah2, ah3, bl[2], bl[3]);
            mma_bf16(acc1, al0, al1, al2, al3, bh[2], bh[3]);
        }
    }

    // softmax on fragments (R11-proven mapping)
    int c_ = lane & 3;
    bool mask15 = (c_ == 3);
#pragma unroll
    for (int half = 0; half < 2; half++) {
        float v0 = acc0[half * 2 + 0] * 0.0625f;
        float v1 = acc0[half * 2 + 1] * 0.0625f;
        float v2 = acc1[half * 2 + 0] * 0.0625f;
        float v3 = mask15 ? -1e30f : acc1[half * 2 + 1] * 0.0625f;
        float mx = fmaxf(fmaxf(v0, v1), fmaxf(v2, v3));
        mx = fmaxf(mx, __shfl_xor_sync(0xffffffffu, mx, 1));
        mx = fmaxf(mx, __shfl_xor_sync(0xffffffffu, mx, 2));
        v0 = __expf(v0 - mx); v1 = __expf(v1 - mx);
        v2 = __expf(v2 - mx); v3 = mask15 ? 0.f : __expf(v3 - mx);
        float sum = v0 + v1 + v2 + v3;
        sum += __shfl_xor_sync(0xffffffffu, sum, 1);
        sum += __shfl_xor_sync(0xffffffffu, sum, 2);
        float inv = 1.0f / sum;
        int n_loc = wid * 16 + (lane >> 2) + half * 8;
        as_[(2 * c_ + 0) * AS2 + n_loc] = v0 * inv;
        as_[(2 * c_ + 1) * AS2 + n_loc] = v1 * inv;
        as_[(8 + 2 * c_) * AS2 + n_loc] = v2 * inv;
        if (!mask15) as_[(9 + 2 * c_) * AS2 + n_loc] = v3 * inv;
    }
    __syncthreads();

    if (final_pass) {
        for (int i = t; i < Kk * CHN; i += 256) {
            int s = i >> 7, n = i & 127;
            attn_out[((size_t)(b * Kk + s)) * Nn + n_glob0 + n] = as_[s * AS2 + n];
        }
        return;
    }

    // partial rowsums (15 threads)
    if (t < Kk) {
        float ps = 0.f;
#pragma unroll 8
        for (int n = 0; n < CHN; n++) ps += as_[t * AS2 + n];
        g_part[(b * Kk + t) * NCH + chunk] = ps;
    }

    // phase 2 (fp32, L2-hot re-read of the same array): thread = d
    float acc[Kk];
#pragma unroll
    for (int s = 0; s < Kk; s++) acc[s] = 0.f;
    const float* xp = xln + ((size_t)b * Nn + n_glob0) * Dd + t;
#pragma unroll 2
    for (int n4 = 0; n4 < CHN / 4; n4++) {
        float x0 = xp[(4 * n4 + 0) * Dd];
        float x1 = xp[(4 * n4 + 1) * Dd];
        float x2 = xp[(4 * n4 + 2) * Dd];
        float x3 = xp[(4 * n4 + 3) * Dd];
#pragma unroll
        for (int s = 0; s < Kk; s++) {
            float4 a4 = *(const float4*)(as_ + s * AS2 + 4 * n4);
            acc[s] += a4.x * x0 + a4.y * x1 + a4.z * x2 + a4.w * x3;
        }
    }
#pragma unroll
    for (int s = 0; s < Kk; s++)
        g_updpart[((size_t)chunk * BK_TOT + b * Kk + s) * Dd + t] = acc[s];
}

// ---------------- fused slot update: U-reduce → GRU → MLP → LN → q ----------------
__global__ __launch_bounds__(256) void slot_update_kernel(
    const float* __restrict__ whh, const float* __restrict__ w1,
    const float* __restrict__ w2,
    const float* __restrict__ bih, const float* __restrict__ bhh,
    const float* __restrict__ b1, const float* __restrict__ b2,
    const float* __restrict__ lnm_w, const float* __restrict__ lnm_b,
    const float* __restrict__ lns_w, const float* __restrict__ lns_b) {
    __shared__ float u_s[8][256];
    __shared__ float h_s[8][256];
    __shared__ float a_s[8][256];
    __shared__ float h1_s[8][512];
    __shared__ float inv_s[8];
    int t = threadIdx.x, lane = t & 31, wid = t >> 5;
    int row0 = blockIdx.x * 8;

#pragma unroll
    for (int r = 0; r < 8; r++) h_s[r][t] = g_slots[(size_t)(row0 + r) * Dd + t];
    if (t < 8) {
        float s = 0.f;
#pragma unroll
        for (int c = 0; c < NCH; c++) s += g_part[(row0 + t) * NCH + c];
        inv_s[t] = 1.0f / (s + 1e-8f);
    }
    __syncthreads();
#pragma unroll
    for (int r = 0; r < 8; r++) {
        float a = 0.f;
#pragma unroll 8
        for (int c = 0; c < NCH; c++)
            a += g_updpart[((size_t)c * BK_TOT + row0 + r) * Dd + t];
        u_s[r][t] = a * inv_s[r];
    }
    __syncthreads();

    float ri[8] = {0}, rh[8] = {0}, zi[8] = {0}, zh[8] = {0}, ni[8] = {0}, nh[8] = {0};
    dot4<64>(ri, &u_s[0][0], 256, g_wiv + (size_t)t * Dd);
    dot4<64>(zi, &u_s[0][0], 256, g_wiv + (size_t)(256 + t) * Dd);
    dot4<64>(ni, &u_s[0][0], 256, g_wiv + (size_t)(512 + t) * Dd);
    dot4<64>(rh, &h_s[0][0], 256, whh + (size_t)t * Dd);
    dot4<64>(zh, &h_s[0][0], 256, whh + (size_t)(256 + t) * Dd);
    dot4<64>(nh, &h_s[0][0], 256, whh + (size_t)(512 + t) * Dd);
    float bir = bih[t], bhr = bhh[t];
    float biz = bih[256 + t], bhz = bhh[256 + t];
    float bin = bih[512 + t], bhn = bhh[512 + t];
    __syncthreads();
#pragma unroll
    for (int r = 0; r < 8; r++) {
        float rg = sigmoidf_(ri[r] + bir + rh[r] + bhr);
        float zg = sigmoidf_(zi[r] + biz + zh[r] + bhz);
        float ng = tanhf(ni[r] + bin + rg * (nh[r] + bhn));
        h_s[r][t] = (1.0f - zg) * ng + zg * h_s[r][t];
    }
    __syncthreads();
    warp_ln_row(&h_s[wid][0], &a_s[wid][0], lnm_w, lnm_b, lane);
    __syncthreads();
    float m0[8] = {0}, m1[8] = {0};
    dot4<64>(m0, &a_s[0][0], 256, w1 + (size_t)t * Dd);
    dot4<64>(m1, &a_s[0][0], 256, w1 + (size_t)(256 + t) * Dd);
    float b1a = b1[t], b1b = b1[256 + t];
#pragma unroll
    for (int r = 0; r < 8; r++) {
        h1_s[r][t] = fmaxf(m0[r] + b1a, 0.f);
        h1_s[r][256 + t] = fmaxf(m1[r] + b1b, 0.f);
    }
    __syncthreads();
    float m2[8] = {0};
    dot4<128>(m2, &h1_s[0][0], 512, w2 + (size_t)t * Hh);
    float b2t = b2[t];
#pragma unroll
    for (int r = 0; r < 8; r++) {
        float ns = h_s[r][t] + m2[r] + b2t;
        g_slots[(size_t)(row0 + r) * Dd + t] = ns;
        a_s[r][t] = ns;
    }
    __syncthreads();
    warp_ln_row(&a_s[wid][0], &u_s[wid][0], lns_w, lns_b, lane);
    __syncthreads();
    float qa[8] = {0};
    dot4<64>(qa, &u_s[0][0], 256, g_wqk + (size_t)t * Dd);
#pragma unroll
    for (int r = 0; r < 8; r++) g_q[(size_t)(row0 + r) * Dd + t] = qa[r];
}

__global__ void copy_kernel(const float* __restrict__ src, float* __restrict__ dst, int n) {
    int i = blockIdx.x * 256 + threadIdx.x;
    if (i < n) dst[i] = src[i];
}

// ---------------- host orchestration ----------------
extern "C" void kernel_launch(void* const* d_in, const int* in_sizes, int n_in,
                              void* d_out, int out_size) {
    const float* inputs        = (const float*)d_in[0];
    const float* slot_noise    = (const float*)d_in[1];
    const float* slots_mu      = (const float*)d_in[2];
    const float* slots_logsig  = (const float*)d_in[3];
    const float* Wq            = (const float*)d_in[4];
    const float* Wk            = (const float*)d_in[5];
    const float* Wv            = (const float*)d_in[6];
    const float* w_ih          = (const float*)d_in[7];
    const float* w_hh          = (const float*)d_in[8];
    const float* b_ih          = (const float*)d_in[9];
    const float* b_hh          = (const float*)d_in[10];
    const float* mlp_w1        = (const float*)d_in[11];
    const float* mlp_b1        = (const float*)d_in[12];
    const float* mlp_w2        = (const float*)d_in[13];
    const float* mlp_b2        = (const float*)d_in[14];
    const float* ln_in_w       = (const float*)d_in[15];
    const float* ln_in_b       = (const float*)d_in[16];
    const float* ln_s_w        = (const float*)d_in[17];
    const float* ln_s_b        = (const float*)d_in[18];
    const float* ln_m_w        = (const float*)d_in[19];
    const float* ln_m_b        = (const float*)d_in[20];
    float* out = (float*)d_out;

    float *p_xln, *p_wqk, *p_wiv, *p_q, *p_slots;
    cudaGetSymbolAddress((void**)&p_xln, g_xln);
    cudaGetSymbolAddress((void**)&p_wqk, g_wqk);
    cudaGetSymbolAddress((void**)&p_wiv, g_wiv);
    cudaGetSymbolAddress((void**)&p_q, g_q);
    cudaGetSymbolAddress((void**)&p_slots, g_slots);

    cudaFuncSetAttribute(attn_pass_kernel,
                         cudaFuncAttributeMaxDynamicSharedMemorySize, SM_BYTES);

    ln_apply_kernel<<<BN_TOT / 8, dim3(32, 8)>>>(inputs, p_xln, ln_in_w, ln_in_b);
    atb_kernel<<<dim3(4, 4), 256>>>(Wk, Wq, p_wqk);
    ab_kernel<<<dim3(12, 4), 256>>>(w_ih, Wv, p_wiv);
    slots_init_kernel<<<BK_TOT, 256>>>(slots_mu, slots_logsig, slot_noise);
    slot_lnq_kernel<<<120, 256>>>(ln_s_w, ln_s_b);

    for (int it = 0; it < 3; it++) {
        attn_pass_kernel<<<dim3(NCH, Bb), 256, SM_BYTES>>>(p_q, p_xln, nullptr, 0);
        slot_update_kernel<<<120, 256>>>(w_hh, mlp_w1, mlp_w2, b_ih, b_hh,
                                         mlp_b1, mlp_b2, ln_m_w, ln_m_b, ln_s_w, ln_s_b);
    }

    attn_pass_kernel<<<dim3(NCH, Bb), 256, SM_BYTES>>>(p_q, p_xln, out + BK_TOT * Dd, 1);
    copy_kernel<<<960, 256>>>(p_slots, out, BK_TOT * Dd);
}